// round 1
// baseline (speedup 1.0000x reference)
#include <cuda_runtime.h>
#include <cuda_bf16.h>
#include <cstdint>
#include <cstddef>

#define B_ 4
#define L_ 1024
#define D_ 1024
#define H_ 16
#define F_ 4096
#define S_ 4
#define LP_ (L_ + 4)

// ---------------- scratch (device globals; no allocation allowed) ----------------
__device__ float g_xpad[B_ * LP_ * D_];
__device__ float g_xc[B_ * L_ * D_];
__device__ float g_sc1[B_ * 512 * D_];
__device__ float g_sc2[B_ * 256 * D_];
__device__ float g_sc3[B_ * 128 * D_];
__device__ float g_qb[B_ * L_ * D_];
__device__ float g_kb[B_ * L_ * D_];
__device__ float g_vb[B_ * L_ * D_];
__device__ float g_ob[B_ * L_ * D_];
__device__ float g_maha[B_ * L_ * D_];
__device__ float g_x1[B_ * L_ * D_];
__device__ float g_ffn[(size_t)B_ * L_ * F_];
__device__ float g_wdcT[3 * D_ * D_];
__device__ float g_wdecT[6 * D_ * D_];
__device__ float g_w[S_];

// ---------------- generic fp32 GEMM: C = act(alpha*(A@B) [+bias] [+C]) --------
// Row remap for conv-as-GEMM: arow = (r/Lout)*Lin + (r%Lout)*strideL + offRow.
// For plain GEMM pass Lout=M, Lin=M, strideL=1, offRow=0 (identity).
__global__ __launch_bounds__(256) void mh_gemm(
    const float* __restrict__ A, const float* __restrict__ B, float* __restrict__ C,
    int M, int N, int K, int lda,
    const float* __restrict__ bias, const float* __restrict__ alphaPtr,
    int accumulate, int act,
    int Lout, int Lin, int strideL, int offRow)
{
    __shared__ __align__(16) float As[16][128];
    __shared__ __align__(16) float Bs[16][128];

    const int tid = threadIdx.x;
    const int tx = tid & 15;   // column group 0..15
    const int ty = tid >> 4;   // row group 0..15
    const int rowBase = blockIdx.y * 128;
    const int colBase = blockIdx.x * 128;

    float alpha = alphaPtr ? __ldg(alphaPtr) : 1.0f;

    float acc[8][8];
#pragma unroll
    for (int i = 0; i < 8; i++)
#pragma unroll
        for (int j = 0; j < 8; j++) acc[i][j] = 0.0f;

    // A tile loading: 128 rows x 16 cols. thread -> row tid>>2 (+64), col (tid&3)*4
    const int aRowL = tid >> 2;
    const int aCol = (tid & 3) * 4;
    // B tile loading: 16 rows(k) x 128 cols. thread -> k tid>>5 (+8), col (tid&31)*4
    const int bK = tid >> 5;
    const int bCol = (tid & 31) * 4;

    int arow0 = -1, arow1 = -1;
    {
        int r0 = rowBase + aRowL;
        int r1 = r0 + 64;
        if (r0 < M) arow0 = (r0 / Lout) * Lin + (r0 % Lout) * strideL + offRow;
        if (r1 < M) arow1 = (r1 / Lout) * Lin + (r1 % Lout) * strideL + offRow;
    }
    const bool bOk = (colBase + bCol) < N;

    for (int k0 = 0; k0 < K; k0 += 16) {
        float4 a0 = make_float4(0.f, 0.f, 0.f, 0.f);
        float4 a1 = a0, b0 = a0, b1 = a0;
        if (arow0 >= 0) a0 = *(const float4*)(A + (size_t)arow0 * lda + k0 + aCol);
        if (arow1 >= 0) a1 = *(const float4*)(A + (size_t)arow1 * lda + k0 + aCol);
        if (bOk) {
            b0 = *(const float4*)(B + (size_t)(k0 + bK) * N + colBase + bCol);
            b1 = *(const float4*)(B + (size_t)(k0 + bK + 8) * N + colBase + bCol);
        }
        __syncthreads();
        As[aCol + 0][aRowL] = a0.x;
        As[aCol + 1][aRowL] = a0.y;
        As[aCol + 2][aRowL] = a0.z;
        As[aCol + 3][aRowL] = a0.w;
        As[aCol + 0][aRowL + 64] = a1.x;
        As[aCol + 1][aRowL + 64] = a1.y;
        As[aCol + 2][aRowL + 64] = a1.z;
        As[aCol + 3][aRowL + 64] = a1.w;
        *(float4*)&Bs[bK][bCol] = b0;
        *(float4*)&Bs[bK + 8][bCol] = b1;
        __syncthreads();

#pragma unroll
        for (int kk = 0; kk < 16; kk++) {
            float4 fa0 = *(const float4*)&As[kk][ty * 8];
            float4 fa1 = *(const float4*)&As[kk][ty * 8 + 4];
            float4 fb0 = *(const float4*)&Bs[kk][tx * 8];
            float4 fb1 = *(const float4*)&Bs[kk][tx * 8 + 4];
            float af[8] = {fa0.x, fa0.y, fa0.z, fa0.w, fa1.x, fa1.y, fa1.z, fa1.w};
            float bf[8] = {fb0.x, fb0.y, fb0.z, fb0.w, fb1.x, fb1.y, fb1.z, fb1.w};
#pragma unroll
            for (int i = 0; i < 8; i++)
#pragma unroll
                for (int j = 0; j < 8; j++) acc[i][j] += af[i] * bf[j];
        }
    }

#pragma unroll
    for (int i = 0; i < 8; i++) {
        int row = rowBase + ty * 8 + i;
        if (row >= M) continue;
#pragma unroll
        for (int j = 0; j < 8; j++) {
            int col = colBase + tx * 8 + j;
            if (col >= N) continue;
            float v = alpha * acc[i][j];
            if (bias) v += bias[col];
            if (accumulate) v += C[(size_t)row * N + col];
            if (act == 1) v = fmaxf(v, 0.0f);
            else if (act == 2) v = 0.5f * v * (1.0f + erff(v * 0.70710678118654752440f));
            C[(size_t)row * N + col] = v;
        }
    }
}

// ---------------- fused attention (flash-style, 16 q x 64 k tiles) ------------
__global__ __launch_bounds__(256) void mh_attn(
    const float* __restrict__ q, const float* __restrict__ k, const float* __restrict__ v,
    float* __restrict__ o, int Ls)
{
    __shared__ __align__(16) float qs[16 * 68];
    __shared__ __align__(16) float ks[64 * 68];
    __shared__ __align__(16) float vs[64 * 68];
    __shared__ __align__(16) float ps[16 * 68];
    __shared__ float s_max[16], s_lsum[16], s_corr[16];

    const int tid = threadIdx.x;
    const int b = blockIdx.z, h = blockIdx.y;
    const int q0 = blockIdx.x * 16;

    // load Q tile (16 rows x 64 dims): exactly 256 float4's
    {
        int r = tid >> 4;
        int dg = (tid & 15) * 4;
        float4 t4 = *(const float4*)(q + ((size_t)(b * L_ + q0 + r) * D_) + h * 64 + dg);
        *(float4*)&qs[r * 68 + dg] = t4;
    }
    if (tid < 16) {
        s_max[tid] = -1e30f;
        s_lsum[tid] = 0.0f;
    }

    float accO[4] = {0.f, 0.f, 0.f, 0.f};
    const int oq = tid >> 4;          // output q row for PV / write
    const int odg = (tid & 15) * 4;   // output dim group
    const int sq = tid & 15;          // S-compute q row
    const int sk0 = (tid >> 4) * 4;   // S-compute key base (4 keys)

    for (int kt = 0; kt < Ls; kt += 64) {
        __syncthreads();  // protect qs/ks/vs/ps from previous phase readers
        // load K,V tiles (64 keys x 64 dims)
#pragma unroll
        for (int it = 0; it < 4; it++) {
            int i = tid + it * 256;
            int key = i >> 4;
            int dg = (i & 15) * 4;
            size_t gidx = ((size_t)(b * Ls + kt + key) * D_) + h * 64 + dg;
            *(float4*)&ks[key * 68 + dg] = *(const float4*)(k + gidx);
            *(float4*)&vs[key * 68 + dg] = *(const float4*)(v + gidx);
        }
        __syncthreads();

        // S = (Q . K^T) * 1/sqrt(dh): each thread does 4 keys for its q row
        {
            float d0 = 0.f, d1 = 0.f, d2 = 0.f, d3 = 0.f;
            const float* qr = &qs[sq * 68];
            const float* k0p = &ks[(sk0 + 0) * 68];
            const float* k1p = &ks[(sk0 + 1) * 68];
            const float* k2p = &ks[(sk0 + 2) * 68];
            const float* k3p = &ks[(sk0 + 3) * 68];
#pragma unroll
            for (int d = 0; d < 64; d += 4) {
                float4 qv = *(const float4*)(qr + d);
                float4 kv;
                kv = *(const float4*)(k0p + d);
                d0 += qv.x * kv.x + qv.y * kv.y + qv.z * kv.z + qv.w * kv.w;
                kv = *(const float4*)(k1p + d);
                d1 += qv.x * kv.x + qv.y * kv.y + qv.z * kv.z + qv.w * kv.w;
                kv = *(const float4*)(k2p + d);
                d2 += qv.x * kv.x + qv.y * kv.y + qv.z * kv.z + qv.w * kv.w;
                kv = *(const float4*)(k3p + d);
                d3 += qv.x * kv.x + qv.y * kv.y + qv.z * kv.z + qv.w * kv.w;
            }
            ps[sq * 68 + sk0 + 0] = d0 * 0.125f;
            ps[sq * 68 + sk0 + 1] = d1 * 0.125f;
            ps[sq * 68 + sk0 + 2] = d2 * 0.125f;
            ps[sq * 68 + sk0 + 3] = d3 * 0.125f;
        }
        __syncthreads();

        // online softmax update: warp w handles rows 2w, 2w+1
        {
            int w = tid >> 5, lane = tid & 31;
#pragma unroll
            for (int rr = 0; rr < 2; rr++) {
                int row = w * 2 + rr;
                float s0 = ps[row * 68 + lane];
                float s1 = ps[row * 68 + lane + 32];
                float m = fmaxf(s0, s1);
#pragma unroll
                for (int off = 16; off; off >>= 1)
                    m = fmaxf(m, __shfl_xor_sync(0xFFFFFFFFu, m, off));
                float oldm = s_max[row];
                float newm = fmaxf(oldm, m);
                float p0 = __expf(s0 - newm);
                float p1 = __expf(s1 - newm);
                ps[row * 68 + lane] = p0;
                ps[row * 68 + lane + 32] = p1;
                float sum = p0 + p1;
#pragma unroll
                for (int off = 16; off; off >>= 1)
                    sum += __shfl_xor_sync(0xFFFFFFFFu, sum, off);
                if (lane == 0) {
                    float corr = __expf(oldm - newm);
                    s_corr[row] = corr;
                    s_lsum[row] = s_lsum[row] * corr + sum;
                    s_max[row] = newm;
                }
            }
        }
        __syncthreads();

        // O = O*corr + P @ V : thread owns (oq, odg..odg+3)
        {
            float corr = s_corr[oq];
            accO[0] *= corr; accO[1] *= corr; accO[2] *= corr; accO[3] *= corr;
            const float* pr = &ps[oq * 68];
#pragma unroll
            for (int key = 0; key < 64; key++) {
                float p = pr[key];
                float4 vv = *(const float4*)&vs[key * 68 + odg];
                accO[0] += p * vv.x;
                accO[1] += p * vv.y;
                accO[2] += p * vv.z;
                accO[3] += p * vv.w;
            }
        }
    }
    __syncthreads();
    float inv = 1.0f / s_lsum[oq];
    float4 outv = make_float4(accO[0] * inv, accO[1] * inv, accO[2] * inv, accO[3] * inv);
    *(float4*)(o + ((size_t)(b * L_ + q0 + oq) * D_) + h * 64 + odg) = outv;
}

// ---------------- LayerNorm(a + b) ----------------
__global__ __launch_bounds__(256) void mh_ln(
    const float* __restrict__ a, const float* __restrict__ bsrc,
    const float* __restrict__ g, const float* __restrict__ be,
    float* __restrict__ out)
{
    __shared__ float r1[256], r2[256];
    int row = blockIdx.x;
    const float* ap = a + (size_t)row * D_;
    const float* bp = bsrc + (size_t)row * D_;
    float x[4];
    float s = 0.f, ss = 0.f;
#pragma unroll
    for (int i = 0; i < 4; i++) {
        int idx = threadIdx.x + i * 256;
        x[i] = ap[idx] + bp[idx];
        s += x[i];
        ss += x[i] * x[i];
    }
    int tid = threadIdx.x;
    r1[tid] = s;
    r2[tid] = ss;
    __syncthreads();
    for (int off = 128; off; off >>= 1) {
        if (tid < off) {
            r1[tid] += r1[tid + off];
            r2[tid] += r2[tid + off];
        }
        __syncthreads();
    }
    float mu = r1[0] * (1.0f / D_);
    float var = r2[0] * (1.0f / D_) - mu * mu;
    float rstd = rsqrtf(var + 1e-5f);
#pragma unroll
    for (int i = 0; i < 4; i++) {
        int idx = threadIdx.x + i * 256;
        out[(size_t)row * D_ + idx] = (x[i] - mu) * rstd * g[idx] + be[idx];
    }
}

// ---------------- misc small kernels ----------------
__global__ void mh_pad(const float* __restrict__ x, float* __restrict__ xpad)
{
    size_t i = (size_t)blockIdx.x * blockDim.x + threadIdx.x;
    if (i >= (size_t)B_ * LP_ * D_) return;
    int d = (int)(i % D_);
    size_t rl = i / D_;
    int l = (int)(rl % LP_);
    int b = (int)(rl / LP_);
    float val = 0.0f;
    if (l >= 2 && l < L_ + 2)
        val = x[((size_t)b * L_ + (l - 2)) * D_ + d];
    xpad[i] = val;
}

// dst[k][i][o] = W_dc[o][i][k]  (W_dc is [D,D,3] OIH)
__global__ void mh_twdc(const float* __restrict__ W, float* __restrict__ out)
{
    size_t i = (size_t)blockIdx.x * blockDim.x + threadIdx.x;
    if (i >= (size_t)3 * D_ * D_) return;
    int o = (int)(i % D_);
    int ii = (int)((i / D_) % D_);
    int kk = (int)(i / ((size_t)D_ * D_));
    out[i] = W[((size_t)o * D_ + ii) * 3 + kk];
}

// dst[s][k][i][o] = W_dec[s][o][i][k]  (W_dec is [3,D,D,2])
__global__ void mh_twdec(const float* __restrict__ W, float* __restrict__ out)
{
    size_t i = (size_t)blockIdx.x * blockDim.x + threadIdx.x;
    if (i >= (size_t)6 * D_ * D_) return;
    int o = (int)(i % D_);
    int ii = (int)((i / D_) % D_);
    int kk = (int)((i / ((size_t)D_ * D_)) % 2);
    int s = (int)(i / ((size_t)2 * D_ * D_));
    out[i] = W[(((size_t)s * D_ + o) * D_ + ii) * 2 + kk];
}

__global__ void mh_agg(const float* __restrict__ logits, float* __restrict__ w,
                       float* __restrict__ aux_out, int has_aux)
{
    if (threadIdx.x == 0 && blockIdx.x == 0) {
        float l[S_], m = -1e30f;
        for (int s = 0; s < S_; s++) { l[s] = logits[s]; m = fmaxf(m, l[s]); }
        float sum = 0.f;
        for (int s = 0; s < S_; s++) { l[s] = expf(l[s] - m); sum += l[s]; }
        float aux = 0.f;
        for (int s = 0; s < S_; s++) {
            float ws = l[s] / sum;
            w[s] = ws;
            aux -= ws * logf(ws + 1e-9f);
        }
        if (has_aux) *aux_out = aux;
    }
}

// ---------------- host launch ----------------
static void launch_gemm(const float* A, const float* B, float* C,
                        int M, int N, int K, int lda,
                        const float* bias, const float* alphaPtr,
                        int accumulate, int act,
                        int Lout, int Lin, int strideL, int offRow)
{
    dim3 grid(N / 128, (M + 127) / 128);
    mh_gemm<<<grid, 256>>>(A, B, C, M, N, K, lda, bias, alphaPtr, accumulate, act,
                           Lout, Lin, strideL, offRow);
}

extern "C" void kernel_launch(void* const* d_in, const int* in_sizes, int n_in,
                              void* d_out, int out_size)
{
    const float* x      = (const float*)d_in[0];
    const float* W_dc   = (const float*)d_in[1];
    const float* b_dc   = (const float*)d_in[2];
    const float* W_dec  = (const float*)d_in[3];
    const float* Wq     = (const float*)d_in[4];
    const float* Wk     = (const float*)d_in[5];
    const float* Wv     = (const float*)d_in[6];
    const float* Wo     = (const float*)d_in[7];
    const float* agl    = (const float*)d_in[8];
    const float* gamma1 = (const float*)d_in[9];
    const float* beta1  = (const float*)d_in[10];
    const float* gamma2 = (const float*)d_in[11];
    const float* beta2  = (const float*)d_in[12];
    const float* W1     = (const float*)d_in[13];
    const float* b1     = (const float*)d_in[14];
    const float* W2     = (const float*)d_in[15];
    const float* b2     = (const float*)d_in[16];
    float* out = (float*)d_out;

    float *xpad, *xc, *sc1, *sc2, *sc3, *qb, *kb, *vb, *ob, *maha, *x1, *ffn;
    float *wdcT, *wdecT, *wagg;
    cudaGetSymbolAddress((void**)&xpad, g_xpad);
    cudaGetSymbolAddress((void**)&xc, g_xc);
    cudaGetSymbolAddress((void**)&sc1, g_sc1);
    cudaGetSymbolAddress((void**)&sc2, g_sc2);
    cudaGetSymbolAddress((void**)&sc3, g_sc3);
    cudaGetSymbolAddress((void**)&qb, g_qb);
    cudaGetSymbolAddress((void**)&kb, g_kb);
    cudaGetSymbolAddress((void**)&vb, g_vb);
    cudaGetSymbolAddress((void**)&ob, g_ob);
    cudaGetSymbolAddress((void**)&maha, g_maha);
    cudaGetSymbolAddress((void**)&x1, g_x1);
    cudaGetSymbolAddress((void**)&ffn, g_ffn);
    cudaGetSymbolAddress((void**)&wdcT, g_wdcT);
    cudaGetSymbolAddress((void**)&wdecT, g_wdecT);
    cudaGetSymbolAddress((void**)&wagg, g_w);

    const int M = B_ * L_;
    const int has_aux = (out_size > B_ * L_ * D_) ? 1 : 0;

    // prep: weight transposes, agg softmax (+aux), padded input
    {
        size_t n = (size_t)3 * D_ * D_;
        mh_twdc<<<(unsigned)((n + 255) / 256), 256>>>(W_dc, wdcT);
        n = (size_t)6 * D_ * D_;
        mh_twdec<<<(unsigned)((n + 255) / 256), 256>>>(W_dec, wdecT);
        mh_agg<<<1, 32>>>(agl, wagg, out + (size_t)B_ * L_ * D_, has_aux);
        n = (size_t)B_ * LP_ * D_;
        mh_pad<<<(unsigned)((n + 255) / 256), 256>>>(x, xpad);
    }

    // 1. dilated conv (3 taps as accumulating GEMMs) + bias + ReLU on last
    for (int t = 0; t < 3; t++) {
        launch_gemm(xpad, wdcT + (size_t)t * D_ * D_, xc, M, D_, D_, D_,
                    (t == 2) ? b_dc : nullptr, nullptr,
                    (t > 0) ? 1 : 0, (t == 2) ? 1 : 0,
                    L_, LP_, 1, 2 * t);
    }

    // 2. hierarchical decomposition (strided convs, 2 taps each)
    const float* scaleP[S_] = {xc, sc1, sc2, sc3};
    int scaleL[S_] = {L_, L_ / 2, L_ / 4, L_ / 8};
    {
        float* outs[3] = {sc1, sc2, sc3};
        for (int s = 0; s < 3; s++) {
            int Lin = scaleL[s], Lout = scaleL[s + 1];
            int Ms = B_ * Lout;
            for (int t = 0; t < 2; t++) {
                launch_gemm(scaleP[s], wdecT + (size_t)(s * 2 + t) * D_ * D_, outs[s],
                            Ms, D_, D_, D_, nullptr, nullptr,
                            t, 0, Lout, Lin, 2, t);
            }
        }
    }

    // 3. multiscale attention + weighted aggregation into maha
    for (int s = 0; s < S_; s++) {
        int Ls = scaleL[s];
        int Mk = B_ * Ls;
        launch_gemm(xc, Wq + (size_t)s * D_ * D_, qb, M, D_, D_, D_,
                    nullptr, nullptr, 0, 0, M, M, 1, 0);
        launch_gemm(scaleP[s], Wk + (size_t)s * D_ * D_, kb, Mk, D_, D_, D_,
                    nullptr, nullptr, 0, 0, Mk, Mk, 1, 0);
        launch_gemm(scaleP[s], Wv, vb, Mk, D_, D_, D_,
                    nullptr, nullptr, 0, 0, Mk, Mk, 1, 0);
        dim3 agrid(L_ / 16, H_, B_);
        mh_attn<<<agrid, 256>>>(qb, kb, vb, ob, Ls);
        // maha (+)= w[s] * (o @ Wo)
        launch_gemm(ob, Wo, maha, M, D_, D_, D_,
                    nullptr, wagg + s, (s > 0) ? 1 : 0, 0, M, M, 1, 0);
    }

    // 4. x1 = LN(residual + maha)
    mh_ln<<<M, 256>>>(x, maha, gamma1, beta1, x1);

    // 5. FFN: gelu(x1@W1+b1)@W2+b2, then out = LN(x1 + ffn)
    launch_gemm(x1, W1, ffn, M, F_, D_, D_, b1, nullptr, 0, 2, M, M, 1, 0);
    launch_gemm(ffn, W2, ob, M, D_, F_, F_, b2, nullptr, 0, 0, M, M, 1, 0);
    mh_ln<<<M, 256>>>(x1, ob, gamma2, beta2, out);
}

// round 5
// speedup vs baseline: 1.9717x; 1.9717x over previous
#include <cuda_runtime.h>
#include <cuda_bf16.h>
#include <cstdint>
#include <cstddef>

#define B_ 4
#define L_ 1024
#define D_ 1024
#define H_ 16
#define F_ 4096
#define S_ 4
#define LP_ (L_ + 4)

// ---------------- scratch (device globals; no allocation allowed) -------------
__device__ float g_xpad[B_ * LP_ * D_];
__device__ float g_xc[B_ * L_ * D_];
__device__ float g_sc1[B_ * 512 * D_];
__device__ float g_sc2[B_ * 256 * D_];
__device__ float g_sc3[B_ * 128 * D_];
__device__ float g_qb[B_ * L_ * D_];
__device__ float g_kb[B_ * L_ * D_];
__device__ float g_vb[B_ * L_ * D_];
__device__ float g_ob[B_ * L_ * D_];
__device__ float g_maha[B_ * L_ * D_];
__device__ float g_x1[B_ * L_ * D_];
__device__ float g_ffn[(size_t)B_ * L_ * F_];
__device__ float g_w[S_];
// transposed weights ([N][K] row-major)
__device__ float g_wdcT[3 * D_ * D_];     // [o][tap][i]
__device__ float g_wdecT[6 * D_ * D_];    // [s][o][tap][i]
__device__ float g_wqT[S_ * D_ * D_];
__device__ float g_wkT[S_ * D_ * D_];
__device__ float g_wvT[D_ * D_];
__device__ float g_woT[D_ * D_];
__device__ float g_w1T[(size_t)D_ * F_];  // [F][D]
__device__ float g_w2T[(size_t)D_ * F_];  // [D][F]

// ---------------- helpers ----------------
__device__ __forceinline__ float tf32r(float x) {
    float r;
    asm("cvt.rna.tf32.f32 %0, %1;" : "=f"(r) : "f"(x));
    return r;
}
__device__ __forceinline__ void mma_tf32(float (&d)[4], const uint32_t (&a)[4],
                                         const uint32_t (&b)[2]) {
    asm volatile(
        "mma.sync.aligned.m16n8k8.row.col.f32.tf32.tf32.f32 "
        "{%0,%1,%2,%3}, {%4,%5,%6,%7}, {%8,%9}, {%0,%1,%2,%3};"
        : "+f"(d[0]), "+f"(d[1]), "+f"(d[2]), "+f"(d[3])
        : "r"(a[0]), "r"(a[1]), "r"(a[2]), "r"(a[3]), "r"(b[0]), "r"(b[1]));
}

#define SSTR 36               // smem row stride in floats (conflict-free frag loads)
#define STAGE_FLOATS (2 * 128 * SSTR)          // As + Bs per stage
#define GEMM_SMEM_BYTES (2 * STAGE_FLOATS * 4) // 73728

// ---------------- tf32 mma.sync GEMM ----------------
// C[M,N] = act(alpha * A' @ BT^T [+bias] [+C])
// A' row remap: arow(r, tap) = (r/Lout)*Lin + (r%Lout)*strideL + offRow + tap*tapOffRow
// k split: tap = k0/KperTap.  BT is [N][Ktot] row-major.
// Requires: M % 128 == 0, N % 128 == 0, Ktot % 32 == 0 (true for all call sites).
__global__ __launch_bounds__(256) void mh_gemm_mma(
    const float* __restrict__ A, const float* __restrict__ BT, float* __restrict__ C,
    int M, int N, int Ktot, int lda, int KperTap, int tapOffRow,
    int Lout, int Lin, int strideL, int offRow,
    const float* __restrict__ bias, const float* __restrict__ alphaPtr,
    int accumulate, int act)
{
    extern __shared__ __align__(16) float dsm[];
    // stage s: As at s*STAGE_FLOATS, Bs at s*STAGE_FLOATS + 128*SSTR
    const int tid = threadIdx.x;
    const int lane = tid & 31;
    const int wid = tid >> 5;
    const int wr = wid >> 2;   // warp row 0..1  (64 rows each)
    const int wc = wid & 3;    // warp col 0..3  (32 cols each)
    const int rowBase = blockIdx.y * 128;
    const int colBase = blockIdx.x * 128;

    // global load mapping: idx = tid + i*256 -> row = idx>>3 (0..127), c4 = idx&7
    const float* aBase[4];
    const float* bBase[4];
    int sRow[4], sC4[4];
#pragma unroll
    for (int i = 0; i < 4; i++) {
        int idx = tid + i * 256;
        int row = idx >> 3, c4 = idx & 7;
        sRow[i] = row; sC4[i] = c4;
        int gr = rowBase + row;
        int ar = (gr / Lout) * Lin + (gr % Lout) * strideL + offRow;
        aBase[i] = A + (size_t)ar * lda + c4 * 4;
        bBase[i] = BT + (size_t)(colBase + row) * Ktot + c4 * 4;
    }

    float acc[4][4][4];
#pragma unroll
    for (int mt = 0; mt < 4; mt++)
#pragma unroll
        for (int nt = 0; nt < 4; nt++)
#pragma unroll
            for (int j = 0; j < 4; j++) acc[mt][nt][j] = 0.0f;

    const int T = Ktot / 32;

    // prologue: fill stage 0
    {
        float* As = dsm;
        float* Bs = dsm + 128 * SSTR;
#pragma unroll
        for (int i = 0; i < 4; i++) {
            float4 av = *(const float4*)(aBase[i]);
            float4 bv = *(const float4*)(bBase[i]);
            float* ap = As + sRow[i] * SSTR + sC4[i] * 4;
            float* bp = Bs + sRow[i] * SSTR + sC4[i] * 4;
            ap[0] = tf32r(av.x); ap[1] = tf32r(av.y); ap[2] = tf32r(av.z); ap[3] = tf32r(av.w);
            bp[0] = tf32r(bv.x); bp[1] = tf32r(bv.y); bp[2] = tf32r(bv.z); bp[3] = tf32r(bv.w);
        }
    }
    __syncthreads();

    const int quad = lane >> 2;     // 0..7
    const int tq = lane & 3;        // 0..3

    for (int t = 0; t < T; t++) {
        const int st = t & 1;
        // prefetch next chunk into registers
        float4 pa[4], pb[4];
        const bool more = (t + 1 < T);
        if (more) {
            int k0 = (t + 1) * 32;
            int tap = k0 / KperTap;
            size_t aAdd = (size_t)tap * tapOffRow * lda + (k0 - tap * KperTap);
#pragma unroll
            for (int i = 0; i < 4; i++) {
                pa[i] = *(const float4*)(aBase[i] + aAdd);
                pb[i] = *(const float4*)(bBase[i] + k0);
            }
        }

        // compute 4 ksteps from stage st
        const float* As = dsm + st * STAGE_FLOATS;
        const float* Bs = As + 128 * SSTR;
#pragma unroll
        for (int ks = 0; ks < 4; ks++) {
            uint32_t af[4][4], bf[4][2];
#pragma unroll
            for (int mt = 0; mt < 4; mt++) {
                int r = wr * 64 + mt * 16 + quad;
                const float* p = As + r * SSTR + ks * 8 + tq;
                af[mt][0] = __float_as_uint(p[0]);
                af[mt][1] = __float_as_uint(p[8 * SSTR]);
                af[mt][2] = __float_as_uint(p[4]);
                af[mt][3] = __float_as_uint(p[8 * SSTR + 4]);
            }
#pragma unroll
            for (int nt = 0; nt < 4; nt++) {
                int n = wc * 32 + nt * 8 + quad;
                const float* p = Bs + n * SSTR + ks * 8 + tq;
                bf[nt][0] = __float_as_uint(p[0]);
                bf[nt][1] = __float_as_uint(p[4]);
            }
#pragma unroll
            for (int mt = 0; mt < 4; mt++)
#pragma unroll
                for (int nt = 0; nt < 4; nt++)
                    mma_tf32(acc[mt][nt], af[mt], bf[nt]);
        }

        if (more) {
            float* As2 = dsm + (st ^ 1) * STAGE_FLOATS;
            float* Bs2 = As2 + 128 * SSTR;
#pragma unroll
            for (int i = 0; i < 4; i++) {
                float* ap = As2 + sRow[i] * SSTR + sC4[i] * 4;
                float* bp = Bs2 + sRow[i] * SSTR + sC4[i] * 4;
                ap[0] = tf32r(pa[i].x); ap[1] = tf32r(pa[i].y);
                ap[2] = tf32r(pa[i].z); ap[3] = tf32r(pa[i].w);
                bp[0] = tf32r(pb[i].x); bp[1] = tf32r(pb[i].y);
                bp[2] = tf32r(pb[i].z); bp[3] = tf32r(pb[i].w);
            }
        }
        __syncthreads();
    }

    // epilogue
    const float alpha = alphaPtr ? __ldg(alphaPtr) : 1.0f;
#pragma unroll
    for (int mt = 0; mt < 4; mt++) {
#pragma unroll
        for (int nt = 0; nt < 4; nt++) {
            int row = rowBase + wr * 64 + mt * 16 + quad;
            int col = colBase + wc * 32 + nt * 8 + tq * 2;
#pragma unroll
            for (int h = 0; h < 2; h++) {
                int r = row + h * 8;
                float v0 = alpha * acc[mt][nt][h * 2 + 0];
                float v1 = alpha * acc[mt][nt][h * 2 + 1];
                if (bias) { v0 += bias[col]; v1 += bias[col + 1]; }
                float* cp = C + (size_t)r * N + col;
                if (accumulate) { v0 += cp[0]; v1 += cp[1]; }
                if (act == 1) { v0 = fmaxf(v0, 0.0f); v1 = fmaxf(v1, 0.0f); }
                else if (act == 2) {
                    v0 = 0.5f * v0 * (1.0f + erff(v0 * 0.70710678118654752440f));
                    v1 = 0.5f * v1 * (1.0f + erff(v1 * 0.70710678118654752440f));
                }
                *(float2*)cp = make_float2(v0, v1);
            }
        }
    }
}

// ---------------- fused attention (flash-style, 16 q x 64 k tiles) ------------
__global__ __launch_bounds__(256) void mh_attn(
    const float* __restrict__ q, const float* __restrict__ k, const float* __restrict__ v,
    float* __restrict__ o, int Ls)
{
    __shared__ __align__(16) float qs[16 * 68];
    __shared__ __align__(16) float ks[64 * 68];
    __shared__ __align__(16) float vs[64 * 68];
    __shared__ __align__(16) float ps[16 * 68];
    __shared__ float s_max[16], s_lsum[16], s_corr[16];

    const int tid = threadIdx.x;
    const int b = blockIdx.z, h = blockIdx.y;
    const int q0 = blockIdx.x * 16;

    {
        int r = tid >> 4;
        int dg = (tid & 15) * 4;
        float4 t4 = *(const float4*)(q + ((size_t)(b * L_ + q0 + r) * D_) + h * 64 + dg);
        *(float4*)&qs[r * 68 + dg] = t4;
    }
    if (tid < 16) { s_max[tid] = -1e30f; s_lsum[tid] = 0.0f; }

    float accO[4] = {0.f, 0.f, 0.f, 0.f};
    const int oq = tid >> 4;
    const int odg = (tid & 15) * 4;
    const int sq = tid & 15;
    const int sk0 = (tid >> 4) * 4;

    for (int kt = 0; kt < Ls; kt += 64) {
        __syncthreads();
#pragma unroll
        for (int it = 0; it < 4; it++) {
            int i = tid + it * 256;
            int key = i >> 4;
            int dg = (i & 15) * 4;
            size_t gidx = ((size_t)(b * Ls + kt + key) * D_) + h * 64 + dg;
            *(float4*)&ks[key * 68 + dg] = *(const float4*)(k + gidx);
            *(float4*)&vs[key * 68 + dg] = *(const float4*)(v + gidx);
        }
        __syncthreads();
        {
            float d0 = 0.f, d1 = 0.f, d2 = 0.f, d3 = 0.f;
            const float* qr = &qs[sq * 68];
            const float* k0p = &ks[(sk0 + 0) * 68];
            const float* k1p = &ks[(sk0 + 1) * 68];
            const float* k2p = &ks[(sk0 + 2) * 68];
            const float* k3p = &ks[(sk0 + 3) * 68];
#pragma unroll
            for (int d = 0; d < 64; d += 4) {
                float4 qv = *(const float4*)(qr + d);
                float4 kv;
                kv = *(const float4*)(k0p + d);
                d0 += qv.x * kv.x + qv.y * kv.y + qv.z * kv.z + qv.w * kv.w;
                kv = *(const float4*)(k1p + d);
                d1 += qv.x * kv.x + qv.y * kv.y + qv.z * kv.z + qv.w * kv.w;
                kv = *(const float4*)(k2p + d);
                d2 += qv.x * kv.x + qv.y * kv.y + qv.z * kv.z + qv.w * kv.w;
                kv = *(const float4*)(k3p + d);
                d3 += qv.x * kv.x + qv.y * kv.y + qv.z * kv.z + qv.w * kv.w;
            }
            ps[sq * 68 + sk0 + 0] = d0 * 0.125f;
            ps[sq * 68 + sk0 + 1] = d1 * 0.125f;
            ps[sq * 68 + sk0 + 2] = d2 * 0.125f;
            ps[sq * 68 + sk0 + 3] = d3 * 0.125f;
        }
        __syncthreads();
        {
            int w = tid >> 5, lane = tid & 31;
#pragma unroll
            for (int rr = 0; rr < 2; rr++) {
                int row = w * 2 + rr;
                float s0 = ps[row * 68 + lane];
                float s1 = ps[row * 68 + lane + 32];
                float m = fmaxf(s0, s1);
#pragma unroll
                for (int off = 16; off; off >>= 1)
                    m = fmaxf(m, __shfl_xor_sync(0xFFFFFFFFu, m, off));
                float oldm = s_max[row];
                float newm = fmaxf(oldm, m);
                float p0 = __expf(s0 - newm);
                float p1 = __expf(s1 - newm);
                ps[row * 68 + lane] = p0;
                ps[row * 68 + lane + 32] = p1;
                float sum = p0 + p1;
#pragma unroll
                for (int off = 16; off; off >>= 1)
                    sum += __shfl_xor_sync(0xFFFFFFFFu, sum, off);
                if (lane == 0) {
                    float corr = __expf(oldm - newm);
                    s_corr[row] = corr;
                    s_lsum[row] = s_lsum[row] * corr + sum;
                    s_max[row] = newm;
                }
            }
        }
        __syncthreads();
        {
            float corr = s_corr[oq];
            accO[0] *= corr; accO[1] *= corr; accO[2] *= corr; accO[3] *= corr;
            const float* pr = &ps[oq * 68];
#pragma unroll
            for (int key = 0; key < 64; key++) {
                float p = pr[key];
                float4 vv = *(const float4*)&vs[key * 68 + odg];
                accO[0] += p * vv.x;
                accO[1] += p * vv.y;
                accO[2] += p * vv.z;
                accO[3] += p * vv.w;
            }
        }
    }
    __syncthreads();
    float inv = 1.0f / s_lsum[oq];
    float4 outv = make_float4(accO[0] * inv, accO[1] * inv, accO[2] * inv, accO[3] * inv);
    *(float4*)(o + ((size_t)(b * L_ + q0 + oq) * D_) + h * 64 + odg) = outv;
}

// ---------------- LayerNorm(a + b) ----------------
__global__ __launch_bounds__(256) void mh_ln(
    const float* __restrict__ a, const float* __restrict__ bsrc,
    const float* __restrict__ g, const float* __restrict__ be,
    float* __restrict__ out)
{
    __shared__ float r1[256], r2[256];
    int row = blockIdx.x;
    const float* ap = a + (size_t)row * D_;
    const float* bp = bsrc + (size_t)row * D_;
    float x[4];
    float s = 0.f, ss = 0.f;
#pragma unroll
    for (int i = 0; i < 4; i++) {
        int idx = threadIdx.x + i * 256;
        x[i] = ap[idx] + bp[idx];
        s += x[i];
        ss += x[i] * x[i];
    }
    int tid = threadIdx.x;
    r1[tid] = s;
    r2[tid] = ss;
    __syncthreads();
    for (int off = 128; off; off >>= 1) {
        if (tid < off) { r1[tid] += r1[tid + off]; r2[tid] += r2[tid + off]; }
        __syncthreads();
    }
    float mu = r1[0] * (1.0f / D_);
    float var = r2[0] * (1.0f / D_) - mu * mu;
    float rstd = rsqrtf(var + 1e-5f);
#pragma unroll
    for (int i = 0; i < 4; i++) {
        int idx = threadIdx.x + i * 256;
        out[(size_t)row * D_ + idx] = (x[i] - mu) * rstd * g[idx] + be[idx];
    }
}

// ---------------- misc small kernels ----------------
__global__ void mh_pad(const float* __restrict__ x, float* __restrict__ xpad)
{
    size_t i = (size_t)blockIdx.x * blockDim.x + threadIdx.x;
    if (i >= (size_t)B_ * LP_ * D_) return;
    int d = (int)(i % D_);
    size_t rl = i / D_;
    int l = (int)(rl % LP_);
    int b = (int)(rl / LP_);
    float val = 0.0f;
    if (l >= 2 && l < L_ + 2)
        val = x[((size_t)b * L_ + (l - 2)) * D_ + d];
    xpad[i] = val;
}

// out[(o*3+t)*1024 + i] = W_dc[(o*1024+i)*3 + t]
__global__ void mh_twdc(const float* __restrict__ W, float* __restrict__ out)
{
    int id = blockIdx.x * 256 + threadIdx.x;
    if (id >= 3 * D_ * D_) return;
    int i = id & (D_ - 1);
    int tmp = id >> 10;
    int t = tmp % 3;
    int o = tmp / 3;
    out[id] = W[((size_t)o * D_ + i) * 3 + t];
}

// out[((s*1024+o)*2+t)*1024 + i] = W_dec[((s*1024+o)*1024+i)*2 + t]
__global__ void mh_twdec(const float* __restrict__ W, float* __restrict__ out)
{
    int id = blockIdx.x * 256 + threadIdx.x;
    if (id >= 6 * D_ * D_) return;
    int i = id & (D_ - 1);
    int tmp = id >> 10;
    int t = tmp & 1;
    tmp >>= 1;
    int o = tmp & (D_ - 1);
    int s = tmp >> 10;
    out[id] = W[(((size_t)s * D_ + o) * D_ + i) * 2 + t];
}

// batched transpose: dst[z][c][r] = src[z][r][c]
__global__ void mh_transpose(const float* __restrict__ src, float* __restrict__ dst,
                             int R, int C)
{
    __shared__ float t[32][33];
    size_t mo = (size_t)blockIdx.z * R * C;
    int x = blockIdx.x * 32 + threadIdx.x;
    int y0 = blockIdx.y * 32 + threadIdx.y;
#pragma unroll
    for (int j = 0; j < 4; j++) {
        int y = y0 + j * 8;
        if (y < R && x < C) t[threadIdx.y + j * 8][threadIdx.x] = src[mo + (size_t)y * C + x];
    }
    __syncthreads();
    int x2 = blockIdx.y * 32 + threadIdx.x;
    int y2 = blockIdx.x * 32 + threadIdx.y;
#pragma unroll
    for (int j = 0; j < 4; j++) {
        int y = y2 + j * 8;
        if (y < C && x2 < R) dst[mo + (size_t)y * R + x2] = t[threadIdx.x][threadIdx.y + j * 8];
    }
}

__global__ void mh_agg(const float* __restrict__ logits, float* __restrict__ w,
                       float* __restrict__ aux_out, int has_aux)
{
    if (threadIdx.x == 0 && blockIdx.x == 0) {
        float l[S_], m = -1e30f;
        for (int s = 0; s < S_; s++) { l[s] = logits[s]; m = fmaxf(m, l[s]); }
        float sum = 0.f;
        for (int s = 0; s < S_; s++) { l[s] = expf(l[s] - m); sum += l[s]; }
        float aux = 0.f;
        for (int s = 0; s < S_; s++) {
            float ws = l[s] / sum;
            w[s] = ws;
            aux -= ws * logf(ws + 1e-9f);
        }
        if (has_aux) *aux_out = aux;
    }
}

// ---------------- host launch ----------------
static void launch_tc(const float* A, const float* BT, float* C,
                      int M, int N, int Ktot, int lda, int KperTap, int tapOffRow,
                      int Lout, int Lin, int strideL, int offRow,
                      const float* bias, const float* alphaPtr,
                      int accumulate, int act)
{
    dim3 grid(N / 128, M / 128);
    mh_gemm_mma<<<grid, 256, GEMM_SMEM_BYTES>>>(
        A, BT, C, M, N, Ktot, lda, KperTap, tapOffRow,
        Lout, Lin, strideL, offRow, bias, alphaPtr, accumulate, act);
}

extern "C" void kernel_launch(void* const* d_in, const int* in_sizes, int n_in,
                              void* d_out, int out_size)
{
    const float* x      = (const float*)d_in[0];
    const float* W_dc   = (const float*)d_in[1];
    const float* b_dc   = (const float*)d_in[2];
    const float* W_dec  = (const float*)d_in[3];
    const float* Wq     = (const float*)d_in[4];
    const float* Wk     = (const float*)d_in[5];
    const float* Wv     = (const float*)d_in[6];
    const float* Wo     = (const float*)d_in[7];
    const float* agl    = (const float*)d_in[8];
    const float* gamma1 = (const float*)d_in[9];
    const float* beta1  = (const float*)d_in[10];
    const float* gamma2 = (const float*)d_in[11];
    const float* beta2  = (const float*)d_in[12];
    const float* W1     = (const float*)d_in[13];
    const float* b1     = (const float*)d_in[14];
    const float* W2     = (const float*)d_in[15];
    const float* b2     = (const float*)d_in[16];
    float* out = (float*)d_out;

    cudaFuncSetAttribute(mh_gemm_mma, cudaFuncAttributeMaxDynamicSharedMemorySize,
                         GEMM_SMEM_BYTES);

    float *xpad, *xc, *sc1, *sc2, *sc3, *qb, *kb, *vb, *ob, *maha, *x1, *ffn, *wagg;
    float *wdcT, *wdecT, *wqT, *wkT, *wvT, *woT, *w1T, *w2T;
    cudaGetSymbolAddress((void**)&xpad, g_xpad);
    cudaGetSymbolAddress((void**)&xc, g_xc);
    cudaGetSymbolAddress((void**)&sc1, g_sc1);
    cudaGetSymbolAddress((void**)&sc2, g_sc2);
    cudaGetSymbolAddress((void**)&sc3, g_sc3);
    cudaGetSymbolAddress((void**)&qb, g_qb);
    cudaGetSymbolAddress((void**)&kb, g_kb);
    cudaGetSymbolAddress((void**)&vb, g_vb);
    cudaGetSymbolAddress((void**)&ob, g_ob);
    cudaGetSymbolAddress((void**)&maha, g_maha);
    cudaGetSymbolAddress((void**)&x1, g_x1);
    cudaGetSymbolAddress((void**)&ffn, g_ffn);
    cudaGetSymbolAddress((void**)&wagg, g_w);
    cudaGetSymbolAddress((void**)&wdcT, g_wdcT);
    cudaGetSymbolAddress((void**)&wdecT, g_wdecT);
    cudaGetSymbolAddress((void**)&wqT, g_wqT);
    cudaGetSymbolAddress((void**)&wkT, g_wkT);
    cudaGetSymbolAddress((void**)&wvT, g_wvT);
    cudaGetSymbolAddress((void**)&woT, g_woT);
    cudaGetSymbolAddress((void**)&w1T, g_w1T);
    cudaGetSymbolAddress((void**)&w2T, g_w2T);

    const int M = B_ * L_;
    const int has_aux = (out_size > B_ * L_ * D_) ? 1 : 0;

    // prep: weight permutes/transposes, agg softmax (+aux), padded input
    mh_twdc<<<(3 * D_ * D_ + 255) / 256, 256>>>(W_dc, wdcT);
    mh_twdec<<<(6 * D_ * D_ + 255) / 256, 256>>>(W_dec, wdecT);
    {
        dim3 tb(32, 8);
        mh_transpose<<<dim3(32, 32, 4), tb>>>(Wq, wqT, D_, D_);
        mh_transpose<<<dim3(32, 32, 4), tb>>>(Wk, wkT, D_, D_);
        mh_transpose<<<dim3(32, 32, 1), tb>>>(Wv, wvT, D_, D_);
        mh_transpose<<<dim3(32, 32, 1), tb>>>(Wo, woT, D_, D_);
        mh_transpose<<<dim3(128, 32, 1), tb>>>(W1, w1T, D_, F_);   // -> [F][D]
        mh_transpose<<<dim3(32, 128, 1), tb>>>(W2, w2T, F_, D_);   // -> [D][F]
    }
    mh_agg<<<1, 32>>>(agl, wagg, out + (size_t)B_ * L_ * D_, has_aux);
    mh_pad<<<(B_ * LP_ * D_ + 255) / 256, 256>>>(x, xpad);

    // 1. dilated conv (3 taps folded into K=3072) + bias + ReLU
    launch_tc(xpad, wdcT, xc, M, D_, 3 * D_, D_, D_, 2,
              L_, LP_, 1, 0, b_dc, nullptr, 0, 1);

    // 2. hierarchical decomposition (2 taps folded into K=2048)
    const float* scaleP[S_] = {xc, sc1, sc2, sc3};
    int scaleL[S_] = {L_, L_ / 2, L_ / 4, L_ / 8};
    {
        float* outs[3] = {sc1, sc2, sc3};
        for (int s = 0; s < 3; s++) {
            int Lin = scaleL[s], Lout = scaleL[s + 1];
            launch_tc(scaleP[s], wdecT + (size_t)s * 2 * D_ * D_, outs[s],
                      B_ * Lout, D_, 2 * D_, D_, D_, 1,
                      Lout, Lin, 2, 0, nullptr, nullptr, 0, 0);
        }
    }

    // 3. multiscale attention + weighted aggregation into maha
    for (int s = 0; s < S_; s++) {
        int Ls = scaleL[s];
        int Mk = B_ * Ls;
        launch_tc(xc, wqT + (size_t)s * D_ * D_, qb, M, D_, D_, D_, D_, 0,
                  M, M, 1, 0, nullptr, nullptr, 0, 0);
        launch_tc(scaleP[s], wkT + (size_t)s * D_ * D_, kb, Mk, D_, D_, D_, D_, 0,
                  Mk, Mk, 1, 0, nullptr, nullptr, 0, 0);
        launch_tc(scaleP[s], wvT, vb, Mk, D_, D_, D_, D_, 0,
                  Mk, Mk, 1, 0, nullptr, nullptr, 0, 0);
        dim3 agrid(L_ / 16, H_, B_);
        mh_attn<<<agrid, 256>>>(qb, kb, vb, ob, Ls);
        launch_tc(ob, woT, maha, M, D_, D_, D_, D_, 0,
                  M, M, 1, 0, nullptr, wagg + s, (s > 0) ? 1 : 0, 0);
    }

    // 4. x1 = LN(residual + maha)
    mh_ln<<<M, 256>>>(x, maha, gamma1, beta1, x1);

    // 5. FFN: gelu(x1@W1+b1)@W2+b2, then out = LN(x1 + ffn)
    launch_tc(x1, w1T, ffn, M, F_, D_, D_, D_, 0, M, M, 1, 0, b1, nullptr, 0, 2);
    launch_tc(ffn, w2T, ob, M, D_, F_, F_, F_, 0, M, M, 1, 0, b2, nullptr, 0, 0);
    mh_ln<<<M, 256>>>(x1, ob, gamma2, beta2, out);
}

// round 7
// speedup vs baseline: 3.5559x; 1.8034x over previous
#include <cuda_runtime.h>
#include <cuda_bf16.h>
#include <cstdint>
#include <cstddef>

#define B_ 4
#define L_ 1024
#define D_ 1024
#define H_ 16
#define F_ 4096
#define S_ 4
#define LP_ (L_ + 4)

// ---------------- scratch (device globals; no allocation allowed) -------------
__device__ float g_xpad[B_ * LP_ * D_];
__device__ float g_xc[B_ * L_ * D_];
__device__ float g_sc1[B_ * 512 * D_];
__device__ float g_sc2[B_ * 256 * D_];
__device__ float g_sc3[B_ * 128 * D_];
__device__ float g_qbig[(size_t)B_ * L_ * (S_ * D_)];   // all-scale Q [row][4096]
__device__ float g_kvb[(size_t)B_ * L_ * 2 * D_];       // K|V fused   [row][2048]
__device__ float g_ob[B_ * L_ * D_];
__device__ float g_maha[B_ * L_ * D_];
__device__ float g_x1[B_ * L_ * D_];
__device__ float g_ffn[(size_t)B_ * L_ * F_];
__device__ float g_w[S_];
// transposed weights ([N][K] row-major)
__device__ float g_wdcT[3 * D_ * D_];                   // [o][tap][i]
__device__ float g_wdecT[6 * D_ * D_];                  // [s][o][tap][i]
__device__ float g_wqT[S_ * D_ * D_];                   // [s*1024+o][i]
__device__ float g_wkvT[(size_t)S_ * 2 * D_ * D_];      // per s: [Wk^T ; Wv^T]
__device__ float g_woT[D_ * D_];
__device__ float g_w1T[(size_t)D_ * F_];                // [F][D]
__device__ float g_w2T[(size_t)D_ * F_];                // [D][F]

// ---------------- helpers ----------------
__device__ __forceinline__ float tf32r(float x) {
    float r;
    asm("cvt.rna.tf32.f32 %0, %1;" : "=f"(r) : "f"(x));
    return r;
}
__device__ __forceinline__ void mma_tf32(float (&d)[4], const uint32_t (&a)[4],
                                         const uint32_t (&b)[2]) {
    asm volatile(
        "mma.sync.aligned.m16n8k8.row.col.f32.tf32.tf32.f32 "
        "{%0,%1,%2,%3}, {%4,%5,%6,%7}, {%8,%9}, {%0,%1,%2,%3};"
        : "+f"(d[0]), "+f"(d[1]), "+f"(d[2]), "+f"(d[3])
        : "r"(a[0]), "r"(a[1]), "r"(a[2]), "r"(a[3]), "r"(b[0]), "r"(b[1]));
}

#define SSTR 36               // GEMM smem row stride (floats)
#define STAGE_FLOATS (2 * 128 * SSTR)
#define GEMM_SMEM_BYTES (2 * STAGE_FLOATS * 4) // 73728

// ---------------- tf32 mma.sync GEMM ----------------
// C[M,N] = act(alpha * A' @ BT^T [+bias] [+C]) ; row remap for conv-as-GEMM.
__global__ __launch_bounds__(256) void mh_gemm_mma(
    const float* __restrict__ A, const float* __restrict__ BT, float* __restrict__ C,
    int M, int N, int Ktot, int lda, int KperTap, int tapOffRow,
    int Lout, int Lin, int strideL, int offRow,
    const float* __restrict__ bias, const float* __restrict__ alphaPtr,
    int accumulate, int act)
{
    extern __shared__ __align__(16) float dsm[];
    const int tid = threadIdx.x;
    const int lane = tid & 31;
    const int wid = tid >> 5;
    const int wr = wid >> 2;
    const int wc = wid & 3;
    const int rowBase = blockIdx.y * 128;
    const int colBase = blockIdx.x * 128;

    const float* aBase[4];
    const float* bBase[4];
    int sRow[4], sC4[4];
#pragma unroll
    for (int i = 0; i < 4; i++) {
        int idx = tid + i * 256;
        int row = idx >> 3, c4 = idx & 7;
        sRow[i] = row; sC4[i] = c4;
        int gr = rowBase + row;
        int ar = (gr / Lout) * Lin + (gr % Lout) * strideL + offRow;
        aBase[i] = A + (size_t)ar * lda + c4 * 4;
        bBase[i] = BT + (size_t)(colBase + row) * Ktot + c4 * 4;
    }

    float acc[4][4][4];
#pragma unroll
    for (int mt = 0; mt < 4; mt++)
#pragma unroll
        for (int nt = 0; nt < 4; nt++)
#pragma unroll
            for (int j = 0; j < 4; j++) acc[mt][nt][j] = 0.0f;

    const int T = Ktot / 32;
    {
        float* As = dsm;
        float* Bs = dsm + 128 * SSTR;
#pragma unroll
        for (int i = 0; i < 4; i++) {
            float4 av = *(const float4*)(aBase[i]);
            float4 bv = *(const float4*)(bBase[i]);
            float* ap = As + sRow[i] * SSTR + sC4[i] * 4;
            float* bp = Bs + sRow[i] * SSTR + sC4[i] * 4;
            ap[0] = tf32r(av.x); ap[1] = tf32r(av.y); ap[2] = tf32r(av.z); ap[3] = tf32r(av.w);
            bp[0] = tf32r(bv.x); bp[1] = tf32r(bv.y); bp[2] = tf32r(bv.z); bp[3] = tf32r(bv.w);
        }
    }
    __syncthreads();

    const int quad = lane >> 2;
    const int tq = lane & 3;

    for (int t = 0; t < T; t++) {
        const int st = t & 1;
        float4 pa[4], pb[4];
        const bool more = (t + 1 < T);
        if (more) {
            int k0 = (t + 1) * 32;
            int tap = k0 / KperTap;
            size_t aAdd = (size_t)tap * tapOffRow * lda + (k0 - tap * KperTap);
#pragma unroll
            for (int i = 0; i < 4; i++) {
                pa[i] = *(const float4*)(aBase[i] + aAdd);
                pb[i] = *(const float4*)(bBase[i] + k0);
            }
        }
        const float* As = dsm + st * STAGE_FLOATS;
        const float* Bs = As + 128 * SSTR;
#pragma unroll
        for (int ks = 0; ks < 4; ks++) {
            uint32_t af[4][4], bf[4][2];
#pragma unroll
            for (int mt = 0; mt < 4; mt++) {
                int r = wr * 64 + mt * 16 + quad;
                const float* p = As + r * SSTR + ks * 8 + tq;
                af[mt][0] = __float_as_uint(p[0]);
                af[mt][1] = __float_as_uint(p[8 * SSTR]);
                af[mt][2] = __float_as_uint(p[4]);
                af[mt][3] = __float_as_uint(p[8 * SSTR + 4]);
            }
#pragma unroll
            for (int nt = 0; nt < 4; nt++) {
                int n = wc * 32 + nt * 8 + quad;
                const float* p = Bs + n * SSTR + ks * 8 + tq;
                bf[nt][0] = __float_as_uint(p[0]);
                bf[nt][1] = __float_as_uint(p[4]);
            }
#pragma unroll
            for (int mt = 0; mt < 4; mt++)
#pragma unroll
                for (int nt = 0; nt < 4; nt++)
                    mma_tf32(acc[mt][nt], af[mt], bf[nt]);
        }
        if (more) {
            float* As2 = dsm + (st ^ 1) * STAGE_FLOATS;
            float* Bs2 = As2 + 128 * SSTR;
#pragma unroll
            for (int i = 0; i < 4; i++) {
                float* ap = As2 + sRow[i] * SSTR + sC4[i] * 4;
                float* bp = Bs2 + sRow[i] * SSTR + sC4[i] * 4;
                ap[0] = tf32r(pa[i].x); ap[1] = tf32r(pa[i].y);
                ap[2] = tf32r(pa[i].z); ap[3] = tf32r(pa[i].w);
                bp[0] = tf32r(pb[i].x); bp[1] = tf32r(pb[i].y);
                bp[2] = tf32r(pb[i].z); bp[3] = tf32r(pb[i].w);
            }
        }
        __syncthreads();
    }

    const float alpha = alphaPtr ? __ldg(alphaPtr) : 1.0f;
#pragma unroll
    for (int mt = 0; mt < 4; mt++) {
#pragma unroll
        for (int nt = 0; nt < 4; nt++) {
            int row = rowBase + wr * 64 + mt * 16 + quad;
            int col = colBase + wc * 32 + nt * 8 + tq * 2;
#pragma unroll
            for (int h = 0; h < 2; h++) {
                int r = row + h * 8;
                float v0 = alpha * acc[mt][nt][h * 2 + 0];
                float v1 = alpha * acc[mt][nt][h * 2 + 1];
                if (bias) { v0 += bias[col]; v1 += bias[col + 1]; }
                float* cp = C + (size_t)r * N + col;
                if (accumulate) { v0 += cp[0]; v1 += cp[1]; }
                if (act == 1) { v0 = fmaxf(v0, 0.0f); v1 = fmaxf(v1, 0.0f); }
                else if (act == 2) {
                    v0 = 0.5f * v0 * (1.0f + erff(v0 * 0.70710678118654752440f));
                    v1 = 0.5f * v1 * (1.0f + erff(v1 * 0.70710678118654752440f));
                }
                *(float2*)cp = make_float2(v0, v1);
            }
        }
    }
}

// ---------------- tensor-core flash attention (64q x 64k tiles) ---------------
// o[row, h*64+d] (+)= alpha * softmax(Q@K^T/8) @ V for one (b, h).
// q: qbig (stride qld, scale offset qoff). kv: fused K|V rows (stride kvld),
// K at col h*64, V at col 1024 + h*64.
#define ASTR 72
#define ATT_SMEM ((4 * 64 * ASTR + 192) * 4)
__global__ __launch_bounds__(128) void mh_attn_mma(
    const float* __restrict__ q, int qld, int qoff,
    const float* __restrict__ kv, int kvld,
    float* __restrict__ o, int Ls,
    const float* __restrict__ alphaPtr, int accumulate)
{
    extern __shared__ __align__(16) float sm[];
    float* qs = sm;                  // 64 x 72
    float* ks = qs + 64 * ASTR;      // 64 x 72
    float* vs = ks + 64 * ASTR;      // 64 x 72
    float* ps = vs + 64 * ASTR;      // 64 x 72 (warp w owns rows w*16..w*16+15)
    float* s_max = ps + 64 * ASTR;   // 64
    float* s_lsum = s_max + 64;      // 64
    float* s_corr = s_lsum + 64;     // 64

    const int tid = threadIdx.x;
    const int lane = tid & 31;
    const int w = tid >> 5;
    const int quad = lane >> 2, tq = lane & 3;
    const int b = blockIdx.z, h = blockIdx.y;
    const int q0 = blockIdx.x * 64;
    const int rbase = w * 16;

    // load Q tile 64x64 (tf32-rounded)
#pragma unroll
    for (int it = 0; it < 8; it++) {
        int i = tid + it * 128;
        int r = i >> 4, dg = (i & 15) * 4;
        float4 t4 = *(const float4*)(q + (size_t)(b * L_ + q0 + r) * qld + qoff + h * 64 + dg);
        float* dst = qs + r * ASTR + dg;
        dst[0] = tf32r(t4.x); dst[1] = tf32r(t4.y);
        dst[2] = tf32r(t4.z); dst[3] = tf32r(t4.w);
    }
    if (tid < 64) { s_max[tid] = -1e30f; s_lsum[tid] = 0.0f; }

    float oacc[8][4];
#pragma unroll
    for (int nt = 0; nt < 8; nt++)
#pragma unroll
        for (int j = 0; j < 4; j++) oacc[nt][j] = 0.0f;

    for (int kt = 0; kt < Ls; kt += 64) {
        __syncthreads();
        // load K,V chunk (64 keys x 64 dims each), tf32-rounded
#pragma unroll
        for (int it = 0; it < 8; it++) {
            int i = tid + it * 128;
            int key = i >> 4, dg = (i & 15) * 4;
            const float* rowp = kv + (size_t)(b * Ls + kt + key) * kvld;
            float4 kt4 = *(const float4*)(rowp + h * 64 + dg);
            float4 vt4 = *(const float4*)(rowp + D_ + h * 64 + dg);
            float* kd = ks + key * ASTR + dg;
            float* vd = vs + key * ASTR + dg;
            kd[0] = tf32r(kt4.x); kd[1] = tf32r(kt4.y);
            kd[2] = tf32r(kt4.z); kd[3] = tf32r(kt4.w);
            vd[0] = tf32r(vt4.x); vd[1] = tf32r(vt4.y);
            vd[2] = tf32r(vt4.z); vd[3] = tf32r(vt4.w);
        }
        __syncthreads();

        // S = Q @ K^T  (warp: 16 q rows x 64 keys)
        float sacc[8][4];
#pragma unroll
        for (int nt = 0; nt < 8; nt++)
#pragma unroll
            for (int j = 0; j < 4; j++) sacc[nt][j] = 0.0f;
#pragma unroll
        for (int k8 = 0; k8 < 8; k8++) {
            uint32_t af[4];
            const float* qp = qs + (rbase + quad) * ASTR + k8 * 8 + tq;
            af[0] = __float_as_uint(qp[0]);
            af[1] = __float_as_uint(qp[8 * ASTR]);
            af[2] = __float_as_uint(qp[4]);
            af[3] = __float_as_uint(qp[8 * ASTR + 4]);
#pragma unroll
            for (int nt = 0; nt < 8; nt++) {
                uint32_t bf[2];
                const float* kp = ks + (nt * 8 + quad) * ASTR + k8 * 8 + tq;
                bf[0] = __float_as_uint(kp[0]);
                bf[1] = __float_as_uint(kp[4]);
                mma_tf32(sacc[nt], af, bf);
            }
        }
        // write scaled S to ps
#pragma unroll
        for (int nt = 0; nt < 8; nt++) {
            float* p0 = ps + (rbase + quad) * ASTR + nt * 8 + 2 * tq;
            float* p1 = ps + (rbase + quad + 8) * ASTR + nt * 8 + 2 * tq;
            *(float2*)p0 = make_float2(sacc[nt][0] * 0.125f, sacc[nt][1] * 0.125f);
            *(float2*)p1 = make_float2(sacc[nt][2] * 0.125f, sacc[nt][3] * 0.125f);
        }
        __syncwarp();

        // online softmax on this warp's 16 rows
        {
            int r = rbase + (lane & 15);
            int half = lane >> 4;
            float* pr = ps + r * ASTR + half * 32;
            float mx = -1e30f;
#pragma unroll
            for (int j = 0; j < 32; j++) mx = fmaxf(mx, pr[j]);
            mx = fmaxf(mx, __shfl_xor_sync(0xFFFFFFFFu, mx, 16));
            float oldm = s_max[r];
            float newm = fmaxf(oldm, mx);
            float sum = 0.0f;
#pragma unroll
            for (int j = 0; j < 32; j++) {
                float p = __expf(pr[j] - newm);
                pr[j] = tf32r(p);
                sum += p;
            }
            sum += __shfl_xor_sync(0xFFFFFFFFu, sum, 16);
            if (half == 0) {
                float corr = __expf(oldm - newm);
                s_corr[r] = corr;
                s_lsum[r] = s_lsum[r] * corr + sum;
                s_max[r] = newm;
            }
        }
        __syncwarp();

        // rescale O, then O += P @ V
        {
            float c0 = s_corr[rbase + quad];
            float c1 = s_corr[rbase + quad + 8];
#pragma unroll
            for (int nt = 0; nt < 8; nt++) {
                oacc[nt][0] *= c0; oacc[nt][1] *= c0;
                oacc[nt][2] *= c1; oacc[nt][3] *= c1;
            }
        }
#pragma unroll
        for (int k8 = 0; k8 < 8; k8++) {
            uint32_t af[4];
            const float* pp = ps + (rbase + quad) * ASTR + k8 * 8 + tq;
            af[0] = __float_as_uint(pp[0]);
            af[1] = __float_as_uint(pp[8 * ASTR]);
            af[2] = __float_as_uint(pp[4]);
            af[3] = __float_as_uint(pp[8 * ASTR + 4]);
#pragma unroll
            for (int nt = 0; nt < 8; nt++) {
                uint32_t bf[2];
                const float* vp = vs + (k8 * 8 + tq) * ASTR + nt * 8 + quad;
                bf[0] = __float_as_uint(vp[0]);
                bf[1] = __float_as_uint(vp[4 * ASTR]);
                mma_tf32(oacc[nt], af, bf);
            }
        }
    }

    // epilogue: normalize, scale by alpha, optional accumulate
    const float alpha = alphaPtr ? __ldg(alphaPtr) : 1.0f;
    const float l0 = alpha / s_lsum[rbase + quad];
    const float l1 = alpha / s_lsum[rbase + quad + 8];
    const int row0 = b * L_ + q0 + rbase + quad;
#pragma unroll
    for (int nt = 0; nt < 8; nt++) {
        int col = h * 64 + nt * 8 + 2 * tq;
        float* p0 = o + (size_t)row0 * D_ + col;
        float* p1 = o + (size_t)(row0 + 8) * D_ + col;
        float2 v0 = make_float2(oacc[nt][0] * l0, oacc[nt][1] * l0);
        float2 v1 = make_float2(oacc[nt][2] * l1, oacc[nt][3] * l1);
        if (accumulate) {
            v0.x += p0[0]; v0.y += p0[1];
            v1.x += p1[0]; v1.y += p1[1];
        }
        *(float2*)p0 = v0;
        *(float2*)p1 = v1;
    }
}

// ---------------- LayerNorm(a + b) ----------------
__global__ __launch_bounds__(256) void mh_ln(
    const float* __restrict__ a, const float* __restrict__ bsrc,
    const float* __restrict__ g, const float* __restrict__ be,
    float* __restrict__ out)
{
    __shared__ float r1[256], r2[256];
    int row = blockIdx.x;
    const float* ap = a + (size_t)row * D_;
    const float* bp = bsrc + (size_t)row * D_;
    float x[4];
    float s = 0.f, ss = 0.f;
#pragma unroll
    for (int i = 0; i < 4; i++) {
        int idx = threadIdx.x + i * 256;
        x[i] = ap[idx] + bp[idx];
        s += x[i];
        ss += x[i] * x[i];
    }
    int tid = threadIdx.x;
    r1[tid] = s;
    r2[tid] = ss;
    __syncthreads();
    for (int off = 128; off; off >>= 1) {
        if (tid < off) { r1[tid] += r1[tid + off]; r2[tid] += r2[tid + off]; }
        __syncthreads();
    }
    float mu = r1[0] * (1.0f / D_);
    float var = r2[0] * (1.0f / D_) - mu * mu;
    float rstd = rsqrtf(var + 1e-5f);
#pragma unroll
    for (int i = 0; i < 4; i++) {
        int idx = threadIdx.x + i * 256;
        out[(size_t)row * D_ + idx] = (x[i] - mu) * rstd * g[idx] + be[idx];
    }
}

// ---------------- misc small kernels ----------------
__global__ void mh_pad(const float* __restrict__ x, float* __restrict__ xpad)
{
    size_t i = (size_t)blockIdx.x * blockDim.x + threadIdx.x;
    if (i >= (size_t)B_ * LP_ * D_) return;
    int d = (int)(i % D_);
    size_t rl = i / D_;
    int l = (int)(rl % LP_);
    int b = (int)(rl / LP_);
    float val = 0.0f;
    if (l >= 2 && l < L_ + 2)
        val = x[((size_t)b * L_ + (l - 2)) * D_ + d];
    xpad[i] = val;
}

__global__ void mh_twdc(const float* __restrict__ W, float* __restrict__ out)
{
    int id = blockIdx.x * 256 + threadIdx.x;
    if (id >= 3 * D_ * D_) return;
    int i = id & (D_ - 1);
    int tmp = id >> 10;
    int t = tmp % 3;
    int o = tmp / 3;
    out[id] = W[((size_t)o * D_ + i) * 3 + t];
}

__global__ void mh_twdec(const float* __restrict__ W, float* __restrict__ out)
{
    int id = blockIdx.x * 256 + threadIdx.x;
    if (id >= 6 * D_ * D_) return;
    int i = id & (D_ - 1);
    int tmp = id >> 10;
    int t = tmp & 1;
    tmp >>= 1;
    int o = tmp & (D_ - 1);
    int s = tmp >> 10;
    out[id] = W[(((size_t)s * D_ + o) * D_ + i) * 2 + t];
}

// batched transpose: dst[z][c][r] = src[z][r][c]
__global__ void mh_transpose(const float* __restrict__ src, float* __restrict__ dst,
                             int R, int C)
{
    __shared__ float t[32][33];
    size_t mo = (size_t)blockIdx.z * R * C;
    int x = blockIdx.x * 32 + threadIdx.x;
    int y0 = blockIdx.y * 32 + threadIdx.y;
#pragma unroll
    for (int j = 0; j < 4; j++) {
        int y = y0 + j * 8;
        if (y < R && x < C) t[threadIdx.y + j * 8][threadIdx.x] = src[mo + (size_t)y * C + x];
    }
    __syncthreads();
    int x2 = blockIdx.y * 32 + threadIdx.x;
    int y2 = blockIdx.x * 32 + threadIdx.y;
#pragma unroll
    for (int j = 0; j < 4; j++) {
        int y = y2 + j * 8;
        if (y < C && x2 < R) dst[mo + (size_t)y * R + x2] = t[threadIdx.x][threadIdx.y + j * 8];
    }
}

__global__ void mh_agg(const float* __restrict__ logits, float* __restrict__ w,
                       float* __restrict__ aux_out, int has_aux)
{
    if (threadIdx.x == 0 && blockIdx.x == 0) {
        float l[S_], m = -1e30f;
        for (int s = 0; s < S_; s++) { l[s] = logits[s]; m = fmaxf(m, l[s]); }
        float sum = 0.f;
        for (int s = 0; s < S_; s++) { l[s] = expf(l[s] - m); sum += l[s]; }
        float aux = 0.f;
        for (int s = 0; s < S_; s++) {
            float ws = l[s] / sum;
            w[s] = ws;
            aux -= ws * logf(ws + 1e-9f);
        }
        if (has_aux) *aux_out = aux;
    }
}

// ---------------- host launch ----------------
static void launch_tc(const float* A, const float* BT, float* C,
                      int M, int N, int Ktot, int lda, int KperTap, int tapOffRow,
                      int Lout, int Lin, int strideL, int offRow,
                      const float* bias, const float* alphaPtr,
                      int accumulate, int act)
{
    dim3 grid(N / 128, M / 128);
    mh_gemm_mma<<<grid, 256, GEMM_SMEM_BYTES>>>(
        A, BT, C, M, N, Ktot, lda, KperTap, tapOffRow,
        Lout, Lin, strideL, offRow, bias, alphaPtr, accumulate, act);
}

extern "C" void kernel_launch(void* const* d_in, const int* in_sizes, int n_in,
                              void* d_out, int out_size)
{
    const float* x      = (const float*)d_in[0];
    const float* W_dc   = (const float*)d_in[1];
    const float* b_dc   = (const float*)d_in[2];
    const float* W_dec  = (const float*)d_in[3];
    const float* Wq     = (const float*)d_in[4];
    const float* Wk     = (const float*)d_in[5];
    const float* Wv     = (const float*)d_in[6];
    const float* Wo     = (const float*)d_in[7];
    const float* agl    = (const float*)d_in[8];
    const float* gamma1 = (const float*)d_in[9];
    const float* beta1  = (const float*)d_in[10];
    const float* gamma2 = (const float*)d_in[11];
    const float* beta2  = (const float*)d_in[12];
    const float* W1     = (const float*)d_in[13];
    const float* b1     = (const float*)d_in[14];
    const float* W2     = (const float*)d_in[15];
    const float* b2     = (const float*)d_in[16];
    float* out = (float*)d_out;

    cudaFuncSetAttribute(mh_gemm_mma, cudaFuncAttributeMaxDynamicSharedMemorySize,
                         GEMM_SMEM_BYTES);
    cudaFuncSetAttribute(mh_attn_mma, cudaFuncAttributeMaxDynamicSharedMemorySize,
                         ATT_SMEM);

    float *xpad, *xc, *sc1, *sc2, *sc3, *qbig, *kvb, *ob, *maha, *x1, *ffn, *wagg;
    float *wdcT, *wdecT, *wqT, *wkvT, *woT, *w1T, *w2T;
    cudaGetSymbolAddress((void**)&xpad, g_xpad);
    cudaGetSymbolAddress((void**)&xc, g_xc);
    cudaGetSymbolAddress((void**)&sc1, g_sc1);
    cudaGetSymbolAddress((void**)&sc2, g_sc2);
    cudaGetSymbolAddress((void**)&sc3, g_sc3);
    cudaGetSymbolAddress((void**)&qbig, g_qbig);
    cudaGetSymbolAddress((void**)&kvb, g_kvb);
    cudaGetSymbolAddress((void**)&ob, g_ob);
    cudaGetSymbolAddress((void**)&maha, g_maha);
    cudaGetSymbolAddress((void**)&x1, g_x1);
    cudaGetSymbolAddress((void**)&ffn, g_ffn);
    cudaGetSymbolAddress((void**)&wagg, g_w);
    cudaGetSymbolAddress((void**)&wdcT, g_wdcT);
    cudaGetSymbolAddress((void**)&wdecT, g_wdecT);
    cudaGetSymbolAddress((void**)&wqT, g_wqT);
    cudaGetSymbolAddress((void**)&wkvT, g_wkvT);
    cudaGetSymbolAddress((void**)&woT, g_woT);
    cudaGetSymbolAddress((void**)&w1T, g_w1T);
    cudaGetSymbolAddress((void**)&w2T, g_w2T);

    const int M = B_ * L_;
    const int has_aux = (out_size > B_ * L_ * D_) ? 1 : 0;
    const size_t DD = (size_t)D_ * D_;

    // prep: weight permutes/transposes, agg softmax (+aux), padded input
    mh_twdc<<<(3 * D_ * D_ + 255) / 256, 256>>>(W_dc, wdcT);
    mh_twdec<<<(6 * D_ * D_ + 255) / 256, 256>>>(W_dec, wdecT);
    {
        dim3 tb(32, 8);
        mh_transpose<<<dim3(32, 32, 4), tb>>>(Wq, wqT, D_, D_);
        for (int s = 0; s < S_; s++) {
            mh_transpose<<<dim3(32, 32, 1), tb>>>(Wk + s * DD, wkvT + (size_t)s * 2 * DD, D_, D_);
            mh_transpose<<<dim3(32, 32, 1), tb>>>(Wv, wkvT + (size_t)s * 2 * DD + DD, D_, D_);
        }
        mh_transpose<<<dim3(32, 32, 1), tb>>>(Wo, woT, D_, D_);
        mh_transpose<<<dim3(128, 32, 1), tb>>>(W1, w1T, D_, F_);   // -> [F][D]
        mh_transpose<<<dim3(32, 128, 1), tb>>>(W2, w2T, F_, D_);   // -> [D][F]
    }
    mh_agg<<<1, 32>>>(agl, wagg, out + (size_t)B_ * L_ * D_, has_aux);
    mh_pad<<<(B_ * LP_ * D_ + 255) / 256, 256>>>(x, xpad);

    // 1. dilated conv (3 taps folded into K=3072) + bias + ReLU
    launch_tc(xpad, wdcT, xc, M, D_, 3 * D_, D_, D_, 2,
              L_, LP_, 1, 0, b_dc, nullptr, 0, 1);

    // 2. hierarchical decomposition (2 taps folded into K=2048)
    const float* scaleP[S_] = {xc, sc1, sc2, sc3};
    int scaleL[S_] = {L_, L_ / 2, L_ / 4, L_ / 8};
    {
        float* outs[3] = {sc1, sc2, sc3};
        for (int s = 0; s < 3; s++) {
            int Lin = scaleL[s], Lout = scaleL[s + 1];
            launch_tc(scaleP[s], wdecT + (size_t)s * 2 * DD, outs[s],
                      B_ * Lout, D_, 2 * D_, D_, D_, 1,
                      Lout, Lin, 2, 0, nullptr, nullptr, 0, 0);
        }
    }

    // 3a. all-scale Q projection in one GEMM: qbig[M][4096]
    launch_tc(xc, wqT, qbig, M, S_ * D_, D_, D_, D_, 0,
              M, M, 1, 0, nullptr, nullptr, 0, 0);

    // 3b. per-scale fused K|V projection + tensor-core attention, aggregating
    //     w_s * o_s directly into ob (Wo applied once afterwards)
    for (int s = 0; s < S_; s++) {
        int Ls = scaleL[s];
        int Mk = B_ * Ls;
        launch_tc(scaleP[s], wkvT + (size_t)s * 2 * DD, kvb, Mk, 2 * D_, D_, D_, D_, 0,
                  Mk, Mk, 1, 0, nullptr, nullptr, 0, 0);
        dim3 agrid(L_ / 64, H_, B_);
        mh_attn_mma<<<agrid, 128, ATT_SMEM>>>(qbig, S_ * D_, s * D_, kvb, 2 * D_,
                                              ob, Ls, wagg + s, (s > 0) ? 1 : 0);
    }

    // 3c. shared output projection once: maha = ob @ Wo
    launch_tc(ob, woT, maha, M, D_, D_, D_, D_, 0,
              M, M, 1, 0, nullptr, nullptr, 0, 0);

    // 4. x1 = LN(residual + maha)
    mh_ln<<<M, 256>>>(x, maha, gamma1, beta1, x1);

    // 5. FFN: gelu(x1@W1+b1)@W2+b2, then out = LN(x1 + ffn)
    launch_tc(x1, w1T, ffn, M, F_, D_, D_, D_, 0, M, M, 1, 0, b1, nullptr, 0, 2);
    launch_tc(ffn, w2T, ob, M, D_, F_, F_, F_, 0, M, M, 1, 0, b2, nullptr, 0, 0);
    mh_ln<<<M, 256>>>(x1, ob, gamma2, beta2, out);
}